// round 5
// baseline (speedup 1.0000x reference)
#include <cuda_runtime.h>
#include <cuda_bf16.h>
#include <cstdint>

// ============================================================================
// TaylorLinearNet2 via HMMA (mma.sync bf16), portable sm_100 target.
//   t = X @ W^T  (M=4096, N=8192, K=1024 fp32), then per-8-col Taylor epilogue.
// split-bf16 folded into one K=3072 GEMM:
//   A' = [Xh | Xh | Xl] (4096 x 3072),  B' = [Wh | Wl | Wh] (8192 x 3072)
// Round 5: 2 CTAs/SM (256 thr, 128x128 tile), BK=64, 3 stages, vector converts.
// ============================================================================

#define M_TOTAL 4096
#define N_TOTAL 8192
#define K_IN    1024
#define KTOT    3072
#define ODIM    1024

#define BM 128
#define BN 128
#define BK 64
#define STAGES 3
#define NCH (KTOT / BK)                // 48

// smem rows: 64 bf16 data + 8 pad = 72 elems = 144 B
// row r starts at bank (36r mod 32)=4r -> 8-row ldmatrix phase covers all banks
#define ROWB 144
#define A_BYTES (BM * ROWB)            // 18432
#define B_BYTES (BN * ROWB)            // 18432
#define STAGE_BYTES (A_BYTES + B_BYTES) // 36864
#define SMEM_TOTAL (STAGES * STAGE_BYTES) // 110592 (108KB) x2 CTA = 216KB/SM

__device__ __align__(128) __nv_bfloat16 g_A[(size_t)M_TOTAL * KTOT]; // 24 MB
__device__ __align__(128) __nv_bfloat16 g_B[(size_t)N_TOTAL * KTOT]; // 48 MB

__device__ __forceinline__ uint32_t smem_u32(const void* p) {
    uint32_t a;
    asm("{ .reg .u64 t; cvta.to.shared.u64 t, %1; cvt.u32.u64 %0, t; }"
        : "=r"(a) : "l"(p));
    return a;
}

#define CP_ASYNC16(dst, src) \
    asm volatile("cp.async.cg.shared.global [%0], [%1], 16;" :: "r"(dst), "l"(src))
#define CP_COMMIT() asm volatile("cp.async.commit_group;" ::: "memory")
#define CP_WAIT(n)  asm volatile("cp.async.wait_group %0;" :: "n"(n) : "memory")

#define LDMATRIX_X4(r0, r1, r2, r3, addr) \
    asm volatile("ldmatrix.sync.aligned.m8n8.x4.shared.b16 {%0,%1,%2,%3}, [%4];" \
                 : "=r"(r0), "=r"(r1), "=r"(r2), "=r"(r3) : "r"(addr))

#define MMA_BF16(acc, a, b0v, b1v) \
    asm volatile("mma.sync.aligned.m16n8k16.row.col.f32.bf16.bf16.f32 " \
                 "{%0,%1,%2,%3}, {%4,%5,%6,%7}, {%8,%9}, {%0,%1,%2,%3};" \
                 : "+f"((acc)[0]), "+f"((acc)[1]), "+f"((acc)[2]), "+f"((acc)[3]) \
                 : "r"((a)[0]), "r"((a)[1]), "r"((a)[2]), "r"((a)[3]), \
                   "r"(b0v), "r"(b1v))

// ============================================================================
// split-bf16 conversion, 8 elements per thread, vectorized I/O
// ============================================================================
__device__ __forceinline__ uint32_t split2(float a, float b, float& la, float& lb) {
    __nv_bfloat16 ha = __float2bfloat16_rn(a), hb = __float2bfloat16_rn(b);
    la = a - __bfloat162float(ha);
    lb = b - __bfloat162float(hb);
    __nv_bfloat162 h; h.x = ha; h.y = hb;
    return *reinterpret_cast<uint32_t*>(&h);
}
__device__ __forceinline__ uint32_t pack2(float a, float b) {
    __nv_bfloat162 h; h.x = __float2bfloat16_rn(a); h.y = __float2bfloat16_rn(b);
    return *reinterpret_cast<uint32_t*>(&h);
}

__global__ void convert_x_kernel(const float* __restrict__ X) {
    int idx = blockIdx.x * blockDim.x + threadIdx.x;   // < M*K/8
    int i8 = idx * 8;
    int m = i8 >> 10, i = i8 & 1023;
    const float4* src = reinterpret_cast<const float4*>(X + (size_t)m * K_IN + i);
    float4 v0 = src[0], v1 = src[1];
    float l[8];
    uint4 hv, lv;
    hv.x = split2(v0.x, v0.y, l[0], l[1]);
    hv.y = split2(v0.z, v0.w, l[2], l[3]);
    hv.z = split2(v1.x, v1.y, l[4], l[5]);
    hv.w = split2(v1.z, v1.w, l[6], l[7]);
    lv.x = pack2(l[0], l[1]); lv.y = pack2(l[2], l[3]);
    lv.z = pack2(l[4], l[5]); lv.w = pack2(l[6], l[7]);
    size_t base = (size_t)m * KTOT + i;
    *reinterpret_cast<uint4*>(g_A + base)             = hv;  // vs Wh
    *reinterpret_cast<uint4*>(g_A + base + K_IN)      = hv;  // vs Wl
    *reinterpret_cast<uint4*>(g_A + base + 2 * K_IN)  = lv;  // vs Wh
}

__global__ void convert_w_kernel(const float* __restrict__ W) {
    int idx = blockIdx.x * blockDim.x + threadIdx.x;   // < N*K/8
    int i8 = idx * 8;
    int n = i8 >> 10, i = i8 & 1023;
    const float4* src = reinterpret_cast<const float4*>(W + (size_t)n * K_IN + i);
    float4 v0 = src[0], v1 = src[1];
    float l[8];
    uint4 hv, lv;
    hv.x = split2(v0.x, v0.y, l[0], l[1]);
    hv.y = split2(v0.z, v0.w, l[2], l[3]);
    hv.z = split2(v1.x, v1.y, l[4], l[5]);
    hv.w = split2(v1.z, v1.w, l[6], l[7]);
    lv.x = pack2(l[0], l[1]); lv.y = pack2(l[2], l[3]);
    lv.z = pack2(l[4], l[5]); lv.w = pack2(l[6], l[7]);
    size_t base = (size_t)n * KTOT + i;
    *reinterpret_cast<uint4*>(g_B + base)             = hv;
    *reinterpret_cast<uint4*>(g_B + base + K_IN)      = lv;
    *reinterpret_cast<uint4*>(g_B + base + 2 * K_IN)  = hv;
}

// ============================================================================
// GEMM + fused Taylor epilogue.
// grid (N/128, M/128) = (64, 32), 256 threads, 2 CTAs/SM.
// Warp grid 2(m) x 4(n); warp tile m64 x n32.
// ============================================================================
__global__ __launch_bounds__(256, 2)
void taylor_hmma_kernel(const float* __restrict__ D0, float* __restrict__ OUT)
{
    extern __shared__ __align__(128) char smem[];
    const uint32_t sb = smem_u32(smem);

    const int tid  = threadIdx.x;
    const int lane = tid & 31;
    const int wid  = tid >> 5;
    const int warp_m = wid >> 2;    // 0..1 -> m offset *64
    const int warp_n = wid & 3;     // 0..3 -> n offset *32

    const int bm = blockIdx.y * BM;
    const int bn = blockIdx.x * BN;

    // ---- cp.async mapping: per matrix, 256 thr cover 128 rows x 8 chunks ----
    const int grow = tid >> 1;          // 0..127
    const int gh   = (tid & 1) * 4;     // first chunk (of 4) this thread moves
    const __nv_bfloat16* gA = g_A + (size_t)(bm + grow) * KTOT + gh * 8;
    const __nv_bfloat16* gB = g_B + (size_t)(bn + grow) * KTOT + gh * 8;
    const uint32_t sAd = sb + grow * ROWB + gh * 16;
    const uint32_t sBd = sb + A_BYTES + grow * ROWB + gh * 16;

    float acc[4][4][4];
    #pragma unroll
    for (int mt = 0; mt < 4; mt++)
        #pragma unroll
        for (int nt = 0; nt < 4; nt++)
            #pragma unroll
            for (int r = 0; r < 4; r++) acc[mt][nt][r] = 0.0f;

    // ldmatrix lane addressing
    const int a_row  = warp_m * 64 + (lane & 15);
    const int a_chnk = lane >> 4;              // kLo / kHi 16B chunk
    const int b_row  = warp_n * 32 + (lane & 7) + ((lane >> 4) & 1) * 8;
    const int b_chnk = (lane >> 3) & 1;

    // ---- pipeline prologue: fill stages 0,1 ----
    #pragma unroll
    for (int s = 0; s < STAGES - 1; s++) {
        const int k0 = s * BK;
        #pragma unroll
        for (int j = 0; j < 4; j++) {
            CP_ASYNC16(sAd + s * STAGE_BYTES + j * 16, gA + k0 + j * 8);
            CP_ASYNC16(sBd + s * STAGE_BYTES + j * 16, gB + k0 + j * 8);
        }
        CP_COMMIT();
    }

    int cs = 0;                 // compute stage
    int ls = STAGES - 1;        // load stage
    for (int i = 0; i < NCH; i++) {
        CP_WAIT(STAGES - 2);
        __syncthreads();

        if (i + STAGES - 1 < NCH) {
            const int k0 = (i + STAGES - 1) * BK;
            #pragma unroll
            for (int j = 0; j < 4; j++) {
                CP_ASYNC16(sAd + ls * STAGE_BYTES + j * 16, gA + k0 + j * 8);
                CP_ASYNC16(sBd + ls * STAGE_BYTES + j * 16, gB + k0 + j * 8);
            }
        }
        CP_COMMIT();            // one group per iteration keeps the ledger simple

        const uint32_t aBase = sb + cs * STAGE_BYTES;
        const uint32_t bBase = aBase + A_BYTES;

        #pragma unroll
        for (int ks = 0; ks < BK / 16; ks++) {       // 4 k16-steps
            uint32_t a[4][4];
            #pragma unroll
            for (int mt = 0; mt < 4; mt++) {
                uint32_t addr = aBase + (a_row + mt * 16) * ROWB
                              + ks * 32 + a_chnk * 16;
                LDMATRIX_X4(a[mt][0], a[mt][1], a[mt][2], a[mt][3], addr);
            }
            uint32_t b[2][4];
            #pragma unroll
            for (int np = 0; np < 2; np++) {
                uint32_t addr = bBase + (b_row + np * 16) * ROWB
                              + ks * 32 + b_chnk * 16;
                LDMATRIX_X4(b[np][0], b[np][1], b[np][2], b[np][3], addr);
            }
            #pragma unroll
            for (int mt = 0; mt < 4; mt++)
                #pragma unroll
                for (int nt = 0; nt < 4; nt++)
                    MMA_BF16(acc[mt][nt], a[mt],
                             b[nt >> 1][(nt & 1) * 2], b[nt >> 1][(nt & 1) * 2 + 1]);
        }
        __syncthreads();

        cs = (cs == STAGES - 1) ? 0 : cs + 1;
        ls = (ls == STAGES - 1) ? 0 : ls + 1;
    }

    // ---- fused Taylor epilogue ----
    // C frag m16n8: c0,c1 -> row lane>>2, cols 2*(lane&3)+{0,1}; c2,c3 -> row+8.
    // Each n8 tile is one o-group; gather its 8 cols across the lane quad.
    const int q = lane & ~3;
    #pragma unroll
    for (int nt = 0; nt < 4; nt++) {
        const int o = blockIdx.x * 16 + warp_n * 4 + nt;
        const float d0v = D0[o];
        #pragma unroll
        for (int mt = 0; mt < 4; mt++) {
            float c0 = acc[mt][nt][0], c1 = acc[mt][nt][1];
            float c2 = acc[mt][nt][2], c3 = acc[mt][nt][3];
            float t0[8], t1[8];
            #pragma unroll
            for (int d2 = 0; d2 < 4; d2++) {
                t0[2 * d2]     = __shfl_sync(0xffffffffu, c0, q + d2);
                t0[2 * d2 + 1] = __shfl_sync(0xffffffffu, c1, q + d2);
                t1[2 * d2]     = __shfl_sync(0xffffffffu, c2, q + d2);
                t1[2 * d2 + 1] = __shfl_sync(0xffffffffu, c3, q + d2);
            }
            float p0 = t0[0], s0 = t0[0];
            float p1 = t1[0], s1 = t1[0];
            #pragma unroll
            for (int d = 1; d < 8; d++) {
                p0 *= t0[d]; s0 += p0;
                p1 *= t1[d]; s1 += p1;
            }
            if ((lane & 3) == 0) {
                const int m0 = bm + warp_m * 64 + mt * 16 + (lane >> 2);
                OUT[(size_t)m0 * ODIM + o]       = d0v + s0;
                OUT[(size_t)(m0 + 8) * ODIM + o] = d0v + s1;
            }
        }
    }
}

// ============================================================================
// host side
// ============================================================================
extern "C" void kernel_launch(void* const* d_in, const int* in_sizes, int n_in,
                              void* d_out, int out_size)
{
    const float* x  = (const float*)d_in[0];   // [4096, 1024]
    const float* wt = (const float*)d_in[1];   // [1024, 8, 1024] = [8192, 1024]
    const float* d0 = (const float*)d_in[2];   // [1, 1024]
    float* out = (float*)d_out;                // [4096, 1024]

    convert_x_kernel<<<(M_TOTAL * K_IN / 8) / 256, 256>>>(x);
    convert_w_kernel<<<(N_TOTAL * K_IN / 8) / 256, 256>>>(wt);

    cudaFuncSetAttribute(taylor_hmma_kernel,
                         cudaFuncAttributeMaxDynamicSharedMemorySize, SMEM_TOTAL);
    dim3 grid(N_TOTAL / BN, M_TOTAL / BM);     // (64, 32)
    taylor_hmma_kernel<<<grid, 256, SMEM_TOTAL>>>(d0, out);
}

// round 7
// speedup vs baseline: 1.0917x; 1.0917x over previous
#include <cuda_runtime.h>
#include <cuda_bf16.h>
#include <cstdint>

// ============================================================================
// TaylorLinearNet2 via HMMA (mma.sync bf16), portable sm_100 target.
//   t = X @ W^T  (M=4096, N=8192, K=1024 fp32), then per-8-col Taylor epilogue.
// split-bf16 folded into one K=3072 GEMM:
//   A' = [Xh | Xh | Xl] (4096 x 3072),  B' = [Wh | Wl | Wh] (8192 x 3072)
// Round 6: round-4 geometry (512 thr, 128x256) but BK=64, 3 stages,
//          ONE barrier per iteration, vectorized converts.
// ============================================================================

#define M_TOTAL 4096
#define N_TOTAL 8192
#define K_IN    1024
#define KTOT    3072
#define ODIM    1024

#define BM 128
#define BN 256
#define BK 64
#define STAGES 3
#define NCH (KTOT / BK)                // 48

// smem rows: 64 bf16 data + 8 pad = 72 elems = 144 B
// row r starts at bank 4r mod 32 -> any 8 consecutive rows cover all 32 banks
#define ROWB 144
#define A_BYTES (BM * ROWB)             // 18432
#define B_BYTES (BN * ROWB)             // 36864
#define STAGE_BYTES (A_BYTES + B_BYTES) // 55296
#define SMEM_TOTAL (STAGES * STAGE_BYTES) // 165888 (162 KB), 1 CTA/SM

__device__ __align__(128) __nv_bfloat16 g_A[(size_t)M_TOTAL * KTOT]; // 24 MB
__device__ __align__(128) __nv_bfloat16 g_B[(size_t)N_TOTAL * KTOT]; // 48 MB

__device__ __forceinline__ uint32_t smem_u32(const void* p) {
    uint32_t a;
    asm("{ .reg .u64 t; cvta.to.shared.u64 t, %1; cvt.u32.u64 %0, t; }"
        : "=r"(a) : "l"(p));
    return a;
}

#define CP_ASYNC16(dst, src) \
    asm volatile("cp.async.cg.shared.global [%0], [%1], 16;" :: "r"(dst), "l"(src))
#define CP_COMMIT() asm volatile("cp.async.commit_group;" ::: "memory")
#define CP_WAIT(n)  asm volatile("cp.async.wait_group %0;" :: "n"(n) : "memory")

#define LDMATRIX_X4(r0, r1, r2, r3, addr) \
    asm volatile("ldmatrix.sync.aligned.m8n8.x4.shared.b16 {%0,%1,%2,%3}, [%4];" \
                 : "=r"(r0), "=r"(r1), "=r"(r2), "=r"(r3) : "r"(addr))

#define MMA_BF16(acc, a, b0v, b1v) \
    asm volatile("mma.sync.aligned.m16n8k16.row.col.f32.bf16.bf16.f32 " \
                 "{%0,%1,%2,%3}, {%4,%5,%6,%7}, {%8,%9}, {%0,%1,%2,%3};" \
                 : "+f"((acc)[0]), "+f"((acc)[1]), "+f"((acc)[2]), "+f"((acc)[3]) \
                 : "r"((a)[0]), "r"((a)[1]), "r"((a)[2]), "r"((a)[3]), \
                   "r"(b0v), "r"(b1v))

// ============================================================================
// split-bf16 conversion, 8 elements per thread, vectorized I/O
// ============================================================================
__device__ __forceinline__ uint32_t split2(float a, float b, float& la, float& lb) {
    __nv_bfloat16 ha = __float2bfloat16_rn(a), hb = __float2bfloat16_rn(b);
    la = a - __bfloat162float(ha);
    lb = b - __bfloat162float(hb);
    __nv_bfloat162 h; h.x = ha; h.y = hb;
    return *reinterpret_cast<uint32_t*>(&h);
}
__device__ __forceinline__ uint32_t pack2(float a, float b) {
    __nv_bfloat162 h; h.x = __float2bfloat16_rn(a); h.y = __float2bfloat16_rn(b);
    return *reinterpret_cast<uint32_t*>(&h);
}

__global__ void convert_x_kernel(const float* __restrict__ X) {
    int idx = blockIdx.x * blockDim.x + threadIdx.x;   // < M*K/8
    int i8 = idx * 8;
    int m = i8 >> 10, i = i8 & 1023;
    const float4* src = reinterpret_cast<const float4*>(X + (size_t)m * K_IN + i);
    float4 v0 = src[0], v1 = src[1];
    float l[8];
    uint4 hv, lv;
    hv.x = split2(v0.x, v0.y, l[0], l[1]);
    hv.y = split2(v0.z, v0.w, l[2], l[3]);
    hv.z = split2(v1.x, v1.y, l[4], l[5]);
    hv.w = split2(v1.z, v1.w, l[6], l[7]);
    lv.x = pack2(l[0], l[1]); lv.y = pack2(l[2], l[3]);
    lv.z = pack2(l[4], l[5]); lv.w = pack2(l[6], l[7]);
    size_t base = (size_t)m * KTOT + i;
    *reinterpret_cast<uint4*>(g_A + base)             = hv;  // vs Wh
    *reinterpret_cast<uint4*>(g_A + base + K_IN)      = hv;  // vs Wl
    *reinterpret_cast<uint4*>(g_A + base + 2 * K_IN)  = lv;  // vs Wh
}

__global__ void convert_w_kernel(const float* __restrict__ W) {
    int idx = blockIdx.x * blockDim.x + threadIdx.x;   // < N*K/8
    int i8 = idx * 8;
    int n = i8 >> 10, i = i8 & 1023;
    const float4* src = reinterpret_cast<const float4*>(W + (size_t)n * K_IN + i);
    float4 v0 = src[0], v1 = src[1];
    float l[8];
    uint4 hv, lv;
    hv.x = split2(v0.x, v0.y, l[0], l[1]);
    hv.y = split2(v0.z, v0.w, l[2], l[3]);
    hv.z = split2(v1.x, v1.y, l[4], l[5]);
    hv.w = split2(v1.z, v1.w, l[6], l[7]);
    lv.x = pack2(l[0], l[1]); lv.y = pack2(l[2], l[3]);
    lv.z = pack2(l[4], l[5]); lv.w = pack2(l[6], l[7]);
    size_t base = (size_t)n * KTOT + i;
    *reinterpret_cast<uint4*>(g_B + base)             = hv;
    *reinterpret_cast<uint4*>(g_B + base + K_IN)      = lv;
    *reinterpret_cast<uint4*>(g_B + base + 2 * K_IN)  = hv;
}

// ============================================================================
// GEMM + fused Taylor epilogue.  grid (N/256, M/128) = (32, 32), 512 threads.
// Warp grid 4(m) x 4(n); warp tile m32 x n64.
// ============================================================================
__global__ __launch_bounds__(512, 1)
void taylor_hmma_kernel(const float* __restrict__ D0, float* __restrict__ OUT)
{
    extern __shared__ __align__(128) char smem[];
    const uint32_t sb = smem_u32(smem);

    const int tid  = threadIdx.x;
    const int lane = tid & 31;
    const int wid  = tid >> 5;
    const int warp_m = wid >> 2;    // 0..3 -> m offset *32
    const int warp_n = wid & 3;     // 0..3 -> n offset *64

    const int bm = blockIdx.y * BM;
    const int bn = blockIdx.x * BN;

    // ---- cp.async mapping (per stage): A 1024 chunks, B 2048 chunks ----
    // A: thread t -> row t>>2, chunks 2*(t&3) .. +1  (32B contiguous)
    // B: thread t -> row t>>1, chunks 4*(t&1) .. +3  (64B contiguous)
    const int arow = tid >> 2;
    const int ac   = (tid & 3) * 2;
    const int brow = tid >> 1;
    const int bc   = (tid & 1) * 4;
    const __nv_bfloat16* gA = g_A + (size_t)(bm + arow) * KTOT + ac * 8;
    const __nv_bfloat16* gB = g_B + (size_t)(bn + brow) * KTOT + bc * 8;
    const uint32_t sAd = sb + arow * ROWB + ac * 16;
    const uint32_t sBd = sb + A_BYTES + brow * ROWB + bc * 16;

    float acc[2][8][4];
    #pragma unroll
    for (int mt = 0; mt < 2; mt++)
        #pragma unroll
        for (int nt = 0; nt < 8; nt++)
            #pragma unroll
            for (int r = 0; r < 4; r++) acc[mt][nt][r] = 0.0f;

    // ldmatrix lane addressing (proven round-4 layout)
    const int a_row  = warp_m * 32 + (lane & 15);
    const int a_chnk = lane >> 4;
    const int b_row  = warp_n * 64 + (lane & 7) + ((lane >> 4) & 1) * 8;
    const int b_chnk = (lane >> 3) & 1;

    // ---- prologue: fill stages 0,1 ----
    #pragma unroll
    for (int s = 0; s < STAGES - 1; s++) {
        const int k0 = s * BK;
        CP_ASYNC16(sAd + s * STAGE_BYTES,      gA + k0);
        CP_ASYNC16(sAd + s * STAGE_BYTES + 16, gA + k0 + 8);
        #pragma unroll
        for (int j = 0; j < 4; j++)
            CP_ASYNC16(sBd + s * STAGE_BYTES + j * 16, gB + k0 + j * 8);
        CP_COMMIT();
    }

    int cs = 0;                 // compute stage
    int ls = STAGES - 1;        // load stage
    for (int i = 0; i < NCH; i++) {
        CP_WAIT(STAGES - 2);
        __syncthreads();        // single barrier per iteration:
                                // also protects the refill below (targets the
                                // stage consumed at iter i-1, finished by now)
        if (i + STAGES - 1 < NCH) {
            const int k0 = (i + STAGES - 1) * BK;
            CP_ASYNC16(sAd + ls * STAGE_BYTES,      gA + k0);
            CP_ASYNC16(sAd + ls * STAGE_BYTES + 16, gA + k0 + 8);
            #pragma unroll
            for (int j = 0; j < 4; j++)
                CP_ASYNC16(sBd + ls * STAGE_BYTES + j * 16, gB + k0 + j * 8);
        }
        CP_COMMIT();            // one group per iteration keeps the ledger fixed

        const uint32_t aBase = sb + cs * STAGE_BYTES;
        const uint32_t bBase = aBase + A_BYTES;

        #pragma unroll
        for (int ks = 0; ks < BK / 16; ks++) {       // 4 k16-steps
            uint32_t a[2][4];
            #pragma unroll
            for (int mt = 0; mt < 2; mt++) {
                uint32_t addr = aBase + (a_row + mt * 16) * ROWB
                              + ks * 32 + a_chnk * 16;
                LDMATRIX_X4(a[mt][0], a[mt][1], a[mt][2], a[mt][3], addr);
            }
            uint32_t b[4][4];
            #pragma unroll
            for (int np = 0; np < 4; np++) {
                uint32_t addr = bBase + (b_row + np * 16) * ROWB
                              + ks * 32 + b_chnk * 16;
                LDMATRIX_X4(b[np][0], b[np][1], b[np][2], b[np][3], addr);
            }
            #pragma unroll
            for (int mt = 0; mt < 2; mt++)
                #pragma unroll
                for (int nt = 0; nt < 8; nt++)
                    MMA_BF16(acc[mt][nt], a[mt],
                             b[nt >> 1][(nt & 1) * 2], b[nt >> 1][(nt & 1) * 2 + 1]);
        }
        // no trailing barrier (see comment at top of loop)

        cs = (cs == STAGES - 1) ? 0 : cs + 1;
        ls = (ls == STAGES - 1) ? 0 : ls + 1;
    }

    // ---- fused Taylor epilogue ----
    // C frag m16n8: c0,c1 -> row lane>>2, cols 2*(lane&3)+{0,1}; c2,c3 -> row+8.
    // Each n8 tile is one o-group; gather its 8 cols across the lane quad.
    const int q = lane & ~3;
    #pragma unroll
    for (int nt = 0; nt < 8; nt++) {
        const int o = blockIdx.x * 32 + warp_n * 8 + nt;
        const float d0v = D0[o];
        #pragma unroll
        for (int mt = 0; mt < 2; mt++) {
            float c0 = acc[mt][nt][0], c1 = acc[mt][nt][1];
            float c2 = acc[mt][nt][2], c3 = acc[mt][nt][3];
            float t0[8], t1[8];
            #pragma unroll
            for (int d2 = 0; d2 < 4; d2++) {
                t0[2 * d2]     = __shfl_sync(0xffffffffu, c0, q + d2);
                t0[2 * d2 + 1] = __shfl_sync(0xffffffffu, c1, q + d2);
                t1[2 * d2]     = __shfl_sync(0xffffffffu, c2, q + d2);
                t1[2 * d2 + 1] = __shfl_sync(0xffffffffu, c3, q + d2);
            }
            float p0 = t0[0], s0 = t0[0];
            float p1 = t1[0], s1 = t1[0];
            #pragma unroll
            for (int d = 1; d < 8; d++) {
                p0 *= t0[d]; s0 += p0;
                p1 *= t1[d]; s1 += p1;
            }
            if ((lane & 3) == 0) {
                const int m0 = bm + warp_m * 32 + mt * 16 + (lane >> 2);
                OUT[(size_t)m0 * ODIM + o]       = d0v + s0;
                OUT[(size_t)(m0 + 8) * ODIM + o] = d0v + s1;
            }
        }
    }
}

// ============================================================================
// host side
// ============================================================================
extern "C" void kernel_launch(void* const* d_in, const int* in_sizes, int n_in,
                              void* d_out, int out_size)
{
    const float* x  = (const float*)d_in[0];   // [4096, 1024]
    const float* wt = (const float*)d_in[1];   // [1024, 8, 1024] = [8192, 1024]
    const float* d0 = (const float*)d_in[2];   // [1, 1024]
    float* out = (float*)d_out;                // [4096, 1024]

    convert_x_kernel<<<(M_TOTAL * K_IN / 8) / 256, 256>>>(x);
    convert_w_kernel<<<(N_TOTAL * K_IN / 8) / 256, 256>>>(wt);

    cudaFuncSetAttribute(taylor_hmma_kernel,
                         cudaFuncAttributeMaxDynamicSharedMemorySize, SMEM_TOTAL);
    dim3 grid(N_TOTAL / BN, M_TOTAL / BM);     // (32, 32)
    taylor_hmma_kernel<<<grid, 512, SMEM_TOTAL>>>(d0, out);
}

// round 8
// speedup vs baseline: 2.2257x; 2.0387x over previous
#include <cuda_runtime.h>
#include <cuda_fp16.h>
#include <cstdint>

// ============================================================================
// TaylorLinearNet2 via HMMA (mma.sync fp16), portable sm_100 target.
//   t = X @ W^T  (M=4096, N=8192, K=1024 fp32), then per-8-col Taylor epilogue.
// fp16 2-term emulation, K folded to 2048:
//   x = xh + xl (two fp16, ~22-bit x);  w -> fp16 (error 2^-11, dominant)
//   A' = [Xh | Xl] (4096 x 2048),  B' = [W | W] virtual (stored once, 8192x1024;
//   loader addresses k mod 1024).  t ~= Xh.W^T + Xl.W^T, rel err ~2e-4.
// Geometry = round-4 proven config: 512 thr, 128x256 tile, BK=32, 4 stages.
// ============================================================================

#define M_TOTAL 4096
#define N_TOTAL 8192
#define K_IN    1024
#define KA      2048            // A operand K ([Xh | Xl])
#define ODIM    1024

#define BM 128
#define BN 256
#define BK 32
#define STAGES 4
#define NCH (KA / BK)           // 64

// smem rows: 32 fp16 data (64B) + 16B pad = 80 B; row r starts bank (20r mod 32)
// -> any 8 consecutive rows hit 8 distinct 4-bank groups: conflict-free
#define ROWB 80
#define A_BYTES (BM * ROWB)             // 10240
#define B_BYTES (BN * ROWB)             // 20480
#define STAGE_BYTES (A_BYTES + B_BYTES) // 30720
#define SMEM_TOTAL (STAGES * STAGE_BYTES) // 122880

__device__ __align__(128) __half g_A[(size_t)M_TOTAL * KA];   // 16 MB
__device__ __align__(128) __half g_B[(size_t)N_TOTAL * K_IN]; // 16 MB

__device__ __forceinline__ uint32_t smem_u32(const void* p) {
    uint32_t a;
    asm("{ .reg .u64 t; cvta.to.shared.u64 t, %1; cvt.u32.u64 %0, t; }"
        : "=r"(a) : "l"(p));
    return a;
}

#define CP_ASYNC16(dst, src) \
    asm volatile("cp.async.cg.shared.global [%0], [%1], 16;" :: "r"(dst), "l"(src))
#define CP_COMMIT() asm volatile("cp.async.commit_group;" ::: "memory")
#define CP_WAIT(n)  asm volatile("cp.async.wait_group %0;" :: "n"(n) : "memory")

#define LDMATRIX_X4(r0, r1, r2, r3, addr) \
    asm volatile("ldmatrix.sync.aligned.m8n8.x4.shared.b16 {%0,%1,%2,%3}, [%4];" \
                 : "=r"(r0), "=r"(r1), "=r"(r2), "=r"(r3) : "r"(addr))

#define MMA_F16(acc, a, b0v, b1v) \
    asm volatile("mma.sync.aligned.m16n8k16.row.col.f32.f16.f16.f32 " \
                 "{%0,%1,%2,%3}, {%4,%5,%6,%7}, {%8,%9}, {%0,%1,%2,%3};" \
                 : "+f"((acc)[0]), "+f"((acc)[1]), "+f"((acc)[2]), "+f"((acc)[3]) \
                 : "r"((a)[0]), "r"((a)[1]), "r"((a)[2]), "r"((a)[3]), \
                   "r"(b0v), "r"(b1v))

// ============================================================================
// conversion kernels (vectorized, 8 elems/thread)
// ============================================================================
__device__ __forceinline__ uint32_t hsplit2(float a, float b, float& la, float& lb) {
    __half ha = __float2half_rn(a), hb = __float2half_rn(b);
    la = a - __half2float(ha);
    lb = b - __half2float(hb);
    __half2 h; h.x = ha; h.y = hb;
    return *reinterpret_cast<uint32_t*>(&h);
}
__device__ __forceinline__ uint32_t hpack2(float a, float b) {
    __half2 h; h.x = __float2half_rn(a); h.y = __float2half_rn(b);
    return *reinterpret_cast<uint32_t*>(&h);
}

__global__ void convert_x_kernel(const float* __restrict__ X) {
    int idx = blockIdx.x * blockDim.x + threadIdx.x;   // < M*K_IN/8
    int i8 = idx * 8;
    int m = i8 >> 10, i = i8 & 1023;
    const float4* src = reinterpret_cast<const float4*>(X + (size_t)m * K_IN + i);
    float4 v0 = src[0], v1 = src[1];
    float l[8];
    uint4 hv, lv;
    hv.x = hsplit2(v0.x, v0.y, l[0], l[1]);
    hv.y = hsplit2(v0.z, v0.w, l[2], l[3]);
    hv.z = hsplit2(v1.x, v1.y, l[4], l[5]);
    hv.w = hsplit2(v1.z, v1.w, l[6], l[7]);
    lv.x = hpack2(l[0], l[1]); lv.y = hpack2(l[2], l[3]);
    lv.z = hpack2(l[4], l[5]); lv.w = hpack2(l[6], l[7]);
    size_t base = (size_t)m * KA + i;
    *reinterpret_cast<uint4*>(g_A + base)        = hv;   // Xh
    *reinterpret_cast<uint4*>(g_A + base + K_IN) = lv;   // Xl
}

__global__ void convert_w_kernel(const float* __restrict__ W) {
    int idx = blockIdx.x * blockDim.x + threadIdx.x;   // < N*K_IN/8
    int i8 = idx * 8;
    const float4* src = reinterpret_cast<const float4*>(W + i8);
    float4 v0 = src[0], v1 = src[1];
    uint4 hv;
    hv.x = hpack2(v0.x, v0.y);
    hv.y = hpack2(v0.z, v0.w);
    hv.z = hpack2(v1.x, v1.y);
    hv.w = hpack2(v1.z, v1.w);
    *reinterpret_cast<uint4*>(g_B + i8) = hv;
}

// ============================================================================
// GEMM + fused Taylor epilogue.  grid (N/256, M/128) = (32, 32), 512 threads.
// Warp grid 4(m) x 4(n); warp tile m32 x n64.  (round-4 structure)
// ============================================================================
__global__ __launch_bounds__(512, 1)
void taylor_hmma_kernel(const float* __restrict__ D0, float* __restrict__ OUT)
{
    extern __shared__ __align__(128) char smem[];
    const uint32_t sb = smem_u32(smem);

    const int tid  = threadIdx.x;
    const int lane = tid & 31;
    const int wid  = tid >> 5;
    const int warp_m = wid >> 2;    // 0..3 -> m offset *32
    const int warp_n = wid & 3;     // 0..3 -> n offset *64

    const int bm = blockIdx.y * BM;
    const int bn = blockIdx.x * BN;

    // ---- cp.async mapping: 3 x 16B per thread per stage (round-4 layout) ----
    const int grow = tid >> 2;          // 0..127
    const int gc   = tid & 3;           // 16B chunk in 64B k-slab
    const __half* gA  = g_A + (size_t)(bm + grow) * KA + gc * 8;
    // B row length is K_IN: the k>=1024 half re-reads the same W (k0 & 1023)
    const __half* gB0 = g_B + (size_t)(bn + grow) * K_IN + gc * 8;
    const __half* gB1 = gB0 + (size_t)128 * K_IN;
    const uint32_t sAd  = sb + grow * ROWB + gc * 16;
    const uint32_t sBd0 = sb + A_BYTES + grow * ROWB + gc * 16;
    const uint32_t sBd1 = sBd0 + 128 * ROWB;

    float acc[2][8][4];
    #pragma unroll
    for (int mt = 0; mt < 2; mt++)
        #pragma unroll
        for (int nt = 0; nt < 8; nt++)
            #pragma unroll
            for (int r = 0; r < 4; r++) acc[mt][nt][r] = 0.0f;

    // ldmatrix lane addressing (proven layout)
    const int a_row  = warp_m * 32 + (lane & 15);
    const int a_chnk = lane >> 4;
    const int b_row  = warp_n * 64 + (lane & 7) + ((lane >> 4) & 1) * 8;
    const int b_chnk = (lane >> 3) & 1;

    // ---- pipeline prologue ----
    #pragma unroll
    for (int s = 0; s < STAGES - 1; s++) {
        const int k0 = s * BK;
        const int kb = k0 & (K_IN - 1);
        CP_ASYNC16(sAd  + s * STAGE_BYTES, gA  + k0);
        CP_ASYNC16(sBd0 + s * STAGE_BYTES, gB0 + kb);
        CP_ASYNC16(sBd1 + s * STAGE_BYTES, gB1 + kb);
        CP_COMMIT();
    }

    for (int i = 0; i < NCH; i++) {
        CP_WAIT(STAGES - 2);
        __syncthreads();

        // refill the slot freed at iteration i-1
        if (i + STAGES - 1 < NCH) {
            const int s  = (i + STAGES - 1) & (STAGES - 1);
            const int k0 = (i + STAGES - 1) * BK;
            const int kb = k0 & (K_IN - 1);
            CP_ASYNC16(sAd  + s * STAGE_BYTES, gA  + k0);
            CP_ASYNC16(sBd0 + s * STAGE_BYTES, gB0 + kb);
            CP_ASYNC16(sBd1 + s * STAGE_BYTES, gB1 + kb);
        }
        CP_COMMIT();   // one group per iteration keeps the ledger fixed

        const uint32_t aBase = sb + (i & (STAGES - 1)) * STAGE_BYTES;
        const uint32_t bBase = aBase + A_BYTES;

        #pragma unroll
        for (int ks = 0; ks < 2; ks++) {            // two k16 steps per BK=32
            uint32_t a[2][4];
            #pragma unroll
            for (int mt = 0; mt < 2; mt++) {
                uint32_t addr = aBase + (a_row + mt * 16) * ROWB
                              + (ks * 2 + a_chnk) * 16;
                LDMATRIX_X4(a[mt][0], a[mt][1], a[mt][2], a[mt][3], addr);
            }
            uint32_t b[4][4];
            #pragma unroll
            for (int np = 0; np < 4; np++) {
                uint32_t addr = bBase + (b_row + np * 16) * ROWB
                              + (ks * 2 + b_chnk) * 16;
                LDMATRIX_X4(b[np][0], b[np][1], b[np][2], b[np][3], addr);
            }
            #pragma unroll
            for (int mt = 0; mt < 2; mt++)
                #pragma unroll
                for (int nt = 0; nt < 8; nt++)
                    MMA_F16(acc[mt][nt], a[mt],
                            b[nt >> 1][(nt & 1) * 2], b[nt >> 1][(nt & 1) * 2 + 1]);
        }
        __syncthreads();
    }

    // ---- fused Taylor epilogue ----
    // C frag m16n8: c0,c1 -> row lane>>2, cols 2*(lane&3)+{0,1}; c2,c3 -> row+8.
    // Each n8 tile is one o-group; gather its 8 cols across the lane quad.
    const int q = lane & ~3;
    #pragma unroll
    for (int nt = 0; nt < 8; nt++) {
        const int o = blockIdx.x * 32 + warp_n * 8 + nt;
        const float d0v = D0[o];
        #pragma unroll
        for (int mt = 0; mt < 2; mt++) {
            float c0 = acc[mt][nt][0], c1 = acc[mt][nt][1];
            float c2 = acc[mt][nt][2], c3 = acc[mt][nt][3];
            float t0[8], t1[8];
            #pragma unroll
            for (int d2 = 0; d2 < 4; d2++) {
                t0[2 * d2]     = __shfl_sync(0xffffffffu, c0, q + d2);
                t0[2 * d2 + 1] = __shfl_sync(0xffffffffu, c1, q + d2);
                t1[2 * d2]     = __shfl_sync(0xffffffffu, c2, q + d2);
                t1[2 * d2 + 1] = __shfl_sync(0xffffffffu, c3, q + d2);
            }
            float p0 = t0[0], s0 = t0[0];
            float p1 = t1[0], s1 = t1[0];
            #pragma unroll
            for (int d = 1; d < 8; d++) {
                p0 *= t0[d]; s0 += p0;
                p1 *= t1[d]; s1 += p1;
            }
            if ((lane & 3) == 0) {
                const int m0 = bm + warp_m * 32 + mt * 16 + (lane >> 2);
                OUT[(size_t)m0 * ODIM + o]       = d0v + s0;
                OUT[(size_t)(m0 + 8) * ODIM + o] = d0v + s1;
            }
        }
    }
}

// ============================================================================
// host side
// ============================================================================
extern "C" void kernel_launch(void* const* d_in, const int* in_sizes, int n_in,
                              void* d_out, int out_size)
{
    const float* x  = (const float*)d_in[0];   // [4096, 1024]
    const float* wt = (const float*)d_in[1];   // [1024, 8, 1024] = [8192, 1024]
    const float* d0 = (const float*)d_in[2];   // [1, 1024]
    float* out = (float*)d_out;                // [4096, 1024]

    convert_x_kernel<<<(M_TOTAL * K_IN / 8) / 256, 256>>>(x);
    convert_w_kernel<<<(N_TOTAL * K_IN / 8) / 256, 256>>>(wt);

    cudaFuncSetAttribute(taylor_hmma_kernel,
                         cudaFuncAttributeMaxDynamicSharedMemorySize, SMEM_TOTAL);
    dim3 grid(N_TOTAL / BN, M_TOTAL / BM);     // (32, 32)
    taylor_hmma_kernel<<<grid, 512, SMEM_TOTAL>>>(d0, out);
}

// round 9
// speedup vs baseline: 3.1446x; 1.4128x over previous
#include <cuda_runtime.h>
#include <cuda_fp16.h>
#include <cstdint>

// ============================================================================
// TaylorLinearNet2 via HMMA (mma.sync fp16), portable sm_100 target.
//   t = X @ W^T  (M=4096, N=8192, K=1024), then per-8-col Taylor epilogue.
// Round 9: PURE fp16, K=1024 (no split terms).
//   Error budget (calibrated round 8): w-rounding alone gave 1.74e-4 final;
//   adding x-rounding (independent, same magnitude) -> ~2.4e-4 << 1e-3.
// Geometry = proven round-4/8 config: 512 thr, 128x256 tile, BK=32, 4 stages.
// ============================================================================

#define M_TOTAL 4096
#define N_TOTAL 8192
#define K_IN    1024
#define ODIM    1024

#define BM 128
#define BN 256
#define BK 32
#define STAGES 4
#define NCH (K_IN / BK)         // 32

// smem rows: 32 fp16 data (64B) + 16B pad = 80 B; row r starts bank (20r mod 32)
// -> any 8 consecutive rows hit 8 distinct 4-bank groups: conflict-free
#define ROWB 80
#define A_BYTES (BM * ROWB)             // 10240
#define B_BYTES (BN * ROWB)             // 20480
#define STAGE_BYTES (A_BYTES + B_BYTES) // 30720
#define SMEM_TOTAL (STAGES * STAGE_BYTES) // 122880

__device__ __align__(128) __half g_A[(size_t)M_TOTAL * K_IN]; // 8 MB
__device__ __align__(128) __half g_B[(size_t)N_TOTAL * K_IN]; // 16 MB

__device__ __forceinline__ uint32_t smem_u32(const void* p) {
    uint32_t a;
    asm("{ .reg .u64 t; cvta.to.shared.u64 t, %1; cvt.u32.u64 %0, t; }"
        : "=r"(a) : "l"(p));
    return a;
}

#define CP_ASYNC16(dst, src) \
    asm volatile("cp.async.cg.shared.global [%0], [%1], 16;" :: "r"(dst), "l"(src))
#define CP_COMMIT() asm volatile("cp.async.commit_group;" ::: "memory")
#define CP_WAIT(n)  asm volatile("cp.async.wait_group %0;" :: "n"(n) : "memory")

#define LDMATRIX_X4(r0, r1, r2, r3, addr) \
    asm volatile("ldmatrix.sync.aligned.m8n8.x4.shared.b16 {%0,%1,%2,%3}, [%4];" \
                 : "=r"(r0), "=r"(r1), "=r"(r2), "=r"(r3) : "r"(addr))

#define MMA_F16(acc, a, b0v, b1v) \
    asm volatile("mma.sync.aligned.m16n8k16.row.col.f32.f16.f16.f32 " \
                 "{%0,%1,%2,%3}, {%4,%5,%6,%7}, {%8,%9}, {%0,%1,%2,%3};" \
                 : "+f"((acc)[0]), "+f"((acc)[1]), "+f"((acc)[2]), "+f"((acc)[3]) \
                 : "r"((a)[0]), "r"((a)[1]), "r"((a)[2]), "r"((a)[3]), \
                   "r"(b0v), "r"(b1v))

// ============================================================================
// conversion kernels (vectorized, 8 elems/thread)
// ============================================================================
__device__ __forceinline__ uint32_t hpack2(float a, float b) {
    __half2 h; h.x = __float2half_rn(a); h.y = __float2half_rn(b);
    return *reinterpret_cast<uint32_t*>(&h);
}

__global__ void convert_x_kernel(const float* __restrict__ X) {
    int idx = blockIdx.x * blockDim.x + threadIdx.x;   // < M*K_IN/8
    int i8 = idx * 8;
    const float4* src = reinterpret_cast<const float4*>(X + i8);
    float4 v0 = src[0], v1 = src[1];
    uint4 hv;
    hv.x = hpack2(v0.x, v0.y);
    hv.y = hpack2(v0.z, v0.w);
    hv.z = hpack2(v1.x, v1.y);
    hv.w = hpack2(v1.z, v1.w);
    *reinterpret_cast<uint4*>(g_A + i8) = hv;
}

__global__ void convert_w_kernel(const float* __restrict__ W) {
    int idx = blockIdx.x * blockDim.x + threadIdx.x;   // < N*K_IN/8
    int i8 = idx * 8;
    const float4* src = reinterpret_cast<const float4*>(W + i8);
    float4 v0 = src[0], v1 = src[1];
    uint4 hv;
    hv.x = hpack2(v0.x, v0.y);
    hv.y = hpack2(v0.z, v0.w);
    hv.z = hpack2(v1.x, v1.y);
    hv.w = hpack2(v1.z, v1.w);
    *reinterpret_cast<uint4*>(g_B + i8) = hv;
}

// ============================================================================
// GEMM + fused Taylor epilogue.  grid (N/256, M/128) = (32, 32), 512 threads.
// Warp grid 4(m) x 4(n); warp tile m32 x n64.
// ============================================================================
__global__ __launch_bounds__(512, 1)
void taylor_hmma_kernel(const float* __restrict__ D0, float* __restrict__ OUT)
{
    extern __shared__ __align__(128) char smem[];
    const uint32_t sb = smem_u32(smem);

    const int tid  = threadIdx.x;
    const int lane = tid & 31;
    const int wid  = tid >> 5;
    const int warp_m = wid >> 2;    // 0..3 -> m offset *32
    const int warp_n = wid & 3;     // 0..3 -> n offset *64

    const int bm = blockIdx.y * BM;
    const int bn = blockIdx.x * BN;

    // ---- cp.async mapping: 3 x 16B per thread per stage ----
    const int grow = tid >> 2;          // 0..127
    const int gc   = tid & 3;           // 16B chunk in 64B k-slab
    const __half* gA  = g_A + (size_t)(bm + grow) * K_IN + gc * 8;
    const __half* gB0 = g_B + (size_t)(bn + grow) * K_IN + gc * 8;
    const __half* gB1 = gB0 + (size_t)128 * K_IN;
    const uint32_t sAd  = sb + grow * ROWB + gc * 16;
    const uint32_t sBd0 = sb + A_BYTES + grow * ROWB + gc * 16;
    const uint32_t sBd1 = sBd0 + 128 * ROWB;

    float acc[2][8][4];
    #pragma unroll
    for (int mt = 0; mt < 2; mt++)
        #pragma unroll
        for (int nt = 0; nt < 8; nt++)
            #pragma unroll
            for (int r = 0; r < 4; r++) acc[mt][nt][r] = 0.0f;

    // ldmatrix lane addressing (proven layout)
    const int a_row  = warp_m * 32 + (lane & 15);
    const int a_chnk = lane >> 4;
    const int b_row  = warp_n * 64 + (lane & 7) + ((lane >> 4) & 1) * 8;
    const int b_chnk = (lane >> 3) & 1;

    // ---- pipeline prologue ----
    #pragma unroll
    for (int s = 0; s < STAGES - 1; s++) {
        const int k0 = s * BK;
        CP_ASYNC16(sAd  + s * STAGE_BYTES, gA  + k0);
        CP_ASYNC16(sBd0 + s * STAGE_BYTES, gB0 + k0);
        CP_ASYNC16(sBd1 + s * STAGE_BYTES, gB1 + k0);
        CP_COMMIT();
    }

    for (int i = 0; i < NCH; i++) {
        CP_WAIT(STAGES - 2);
        __syncthreads();

        // refill the slot freed at iteration i-1
        if (i + STAGES - 1 < NCH) {
            const int s  = (i + STAGES - 1) & (STAGES - 1);
            const int k0 = (i + STAGES - 1) * BK;
            CP_ASYNC16(sAd  + s * STAGE_BYTES, gA  + k0);
            CP_ASYNC16(sBd0 + s * STAGE_BYTES, gB0 + k0);
            CP_ASYNC16(sBd1 + s * STAGE_BYTES, gB1 + k0);
        }
        CP_COMMIT();   // one group per iteration keeps the ledger fixed

        const uint32_t aBase = sb + (i & (STAGES - 1)) * STAGE_BYTES;
        const uint32_t bBase = aBase + A_BYTES;

        #pragma unroll
        for (int ks = 0; ks < 2; ks++) {            // two k16 steps per BK=32
            uint32_t a[2][4];
            #pragma unroll
            for (int mt = 0; mt < 2; mt++) {
                uint32_t addr = aBase + (a_row + mt * 16) * ROWB
                              + (ks * 2 + a_chnk) * 16;
                LDMATRIX_X4(a[mt][0], a[mt][1], a[mt][2], a[mt][3], addr);
            }
            uint32_t b[4][4];
            #pragma unroll
            for (int np = 0; np < 4; np++) {
                uint32_t addr = bBase + (b_row + np * 16) * ROWB
                              + (ks * 2 + b_chnk) * 16;
                LDMATRIX_X4(b[np][0], b[np][1], b[np][2], b[np][3], addr);
            }
            #pragma unroll
            for (int mt = 0; mt < 2; mt++)
                #pragma unroll
                for (int nt = 0; nt < 8; nt++)
                    MMA_F16(acc[mt][nt], a[mt],
                            b[nt >> 1][(nt & 1) * 2], b[nt >> 1][(nt & 1) * 2 + 1]);
        }
        __syncthreads();
    }

    // ---- fused Taylor epilogue ----
    // C frag m16n8: c0,c1 -> row lane>>2, cols 2*(lane&3)+{0,1}; c2,c3 -> row+8.
    // Each n8 tile is one o-group; gather its 8 cols across the lane quad.
    const int q = lane & ~3;
    #pragma unroll
    for (int nt = 0; nt < 8; nt++) {
        const int o = blockIdx.x * 32 + warp_n * 8 + nt;
        const float d0v = D0[o];
        #pragma unroll
        for (int mt = 0; mt < 2; mt++) {
            float c0 = acc[mt][nt][0], c1 = acc[mt][nt][1];
            float c2 = acc[mt][nt][2], c3 = acc[mt][nt][3];
            float t0[8], t1[8];
            #pragma unroll
            for (int d2 = 0; d2 < 4; d2++) {
                t0[2 * d2]     = __shfl_sync(0xffffffffu, c0, q + d2);
                t0[2 * d2 + 1] = __shfl_sync(0xffffffffu, c1, q + d2);
                t1[2 * d2]     = __shfl_sync(0xffffffffu, c2, q + d2);
                t1[2 * d2 + 1] = __shfl_sync(0xffffffffu, c3, q + d2);
            }
            float p0 = t0[0], s0 = t0[0];
            float p1 = t1[0], s1 = t1[0];
            #pragma unroll
            for (int d = 1; d < 8; d++) {
                p0 *= t0[d]; s0 += p0;
                p1 *= t1[d]; s1 += p1;
            }
            if ((lane & 3) == 0) {
                const int m0 = bm + warp_m * 32 + mt * 16 + (lane >> 2);
                OUT[(size_t)m0 * ODIM + o]       = d0v + s0;
                OUT[(size_t)(m0 + 8) * ODIM + o] = d0v + s1;
            }
        }
    }
}

// ============================================================================
// host side
// ============================================================================
extern "C" void kernel_launch(void* const* d_in, const int* in_sizes, int n_in,
                              void* d_out, int out_size)
{
    const float* x  = (const float*)d_in[0];   // [4096, 1024]
    const float* wt = (const float*)d_in[1];   // [1024, 8, 1024] = [8192, 1024]
    const float* d0 = (const float*)d_in[2];   // [1, 1024]
    float* out = (float*)d_out;                // [4096, 1024]

    convert_x_kernel<<<(M_TOTAL * K_IN / 8) / 256, 256>>>(x);
    convert_w_kernel<<<(N_TOTAL * K_IN / 8) / 256, 256>>>(wt);

    cudaFuncSetAttribute(taylor_hmma_kernel,
                         cudaFuncAttributeMaxDynamicSharedMemorySize, SMEM_TOTAL);
    dim3 grid(N_TOTAL / BN, M_TOTAL / BM);     // (32, 32)
    taylor_hmma_kernel<<<grid, 512, SMEM_TOTAL>>>(d0, out);
}

// round 10
// speedup vs baseline: 3.5165x; 1.1183x over previous
#include <cuda_runtime.h>
#include <cuda_fp16.h>
#include <cstdint>

// ============================================================================
// TaylorLinearNet2 via HMMA (mma.sync fp16), portable sm_100 target.
//   t = X @ W^T  (M=4096, N=8192, K=1024), then per-8-col Taylor epilogue.
// Pure fp16 operands (calibrated rel_err 2.63e-4 << 1e-3).
// Round 10: merged single-launch convert (MLP=4), STAGES=5; GEMM core = proven
//           round-4/8/9 config (512 thr, 128x256 tile, BK=32).
// ============================================================================

#define M_TOTAL 4096
#define N_TOTAL 8192
#define K_IN    1024
#define ODIM    1024

#define BM 128
#define BN 256
#define BK 32
#define STAGES 5
#define NCH (K_IN / BK)         // 32

// smem rows: 32 fp16 data (64B) + 16B pad = 80 B; row r starts bank (20r mod 32)
// -> any 8 consecutive rows hit 8 distinct 4-bank groups: conflict-free
#define ROWB 80
#define A_BYTES (BM * ROWB)             // 10240
#define B_BYTES (BN * ROWB)             // 20480
#define STAGE_BYTES (A_BYTES + B_BYTES) // 30720
#define SMEM_TOTAL (STAGES * STAGE_BYTES) // 153600

__device__ __align__(128) __half g_A[(size_t)M_TOTAL * K_IN]; // 8 MB
__device__ __align__(128) __half g_B[(size_t)N_TOTAL * K_IN]; // 16 MB

__device__ __forceinline__ uint32_t smem_u32(const void* p) {
    uint32_t a;
    asm("{ .reg .u64 t; cvta.to.shared.u64 t, %1; cvt.u32.u64 %0, t; }"
        : "=r"(a) : "l"(p));
    return a;
}

#define CP_ASYNC16(dst, src) \
    asm volatile("cp.async.cg.shared.global [%0], [%1], 16;" :: "r"(dst), "l"(src))
#define CP_COMMIT() asm volatile("cp.async.commit_group;" ::: "memory")
#define CP_WAIT(n)  asm volatile("cp.async.wait_group %0;" :: "n"(n) : "memory")

#define LDMATRIX_X4(r0, r1, r2, r3, addr) \
    asm volatile("ldmatrix.sync.aligned.m8n8.x4.shared.b16 {%0,%1,%2,%3}, [%4];" \
                 : "=r"(r0), "=r"(r1), "=r"(r2), "=r"(r3) : "r"(addr))

#define MMA_F16(acc, a, b0v, b1v) \
    asm volatile("mma.sync.aligned.m16n8k16.row.col.f32.f16.f16.f32 " \
                 "{%0,%1,%2,%3}, {%4,%5,%6,%7}, {%8,%9}, {%0,%1,%2,%3};" \
                 : "+f"((acc)[0]), "+f"((acc)[1]), "+f"((acc)[2]), "+f"((acc)[3]) \
                 : "r"((a)[0]), "r"((a)[1]), "r"((a)[2]), "r"((a)[3]), \
                   "r"(b0v), "r"(b1v))

// ============================================================================
// merged conversion kernel: 16 elems/thread, 4 independent float4 loads (MLP=4)
//   blocks [0, 1024)    -> X  (4M elems)  into g_A
//   blocks [1024, 3072) -> W  (8M elems)  into g_B
// ============================================================================
__device__ __forceinline__ uint32_t hpack2(float a, float b) {
    __half2 h; h.x = __float2half_rn(a); h.y = __float2half_rn(b);
    return *reinterpret_cast<uint32_t*>(&h);
}

__device__ __forceinline__ void cvt16(const float* __restrict__ src,
                                      __half* __restrict__ dst, size_t base) {
    const float4* s4 = reinterpret_cast<const float4*>(src + base);
    float4 v0 = s4[0], v1 = s4[1], v2 = s4[2], v3 = s4[3];   // 4-wide MLP
    uint4 h0, h1;
    h0.x = hpack2(v0.x, v0.y);  h0.y = hpack2(v0.z, v0.w);
    h0.z = hpack2(v1.x, v1.y);  h0.w = hpack2(v1.z, v1.w);
    h1.x = hpack2(v2.x, v2.y);  h1.y = hpack2(v2.z, v2.w);
    h1.z = hpack2(v3.x, v3.y);  h1.w = hpack2(v3.z, v3.w);
    *reinterpret_cast<uint4*>(dst + base)     = h0;
    *reinterpret_cast<uint4*>(dst + base + 8) = h1;
}

#define X_BLOCKS 1024   // 1024 * 256 * 16 = 4,194,304 = M*K
#define W_BLOCKS 2048   // 2048 * 256 * 16 = 8,388,608 = N*K

__global__ void convert_kernel(const float* __restrict__ X,
                               const float* __restrict__ W) {
    if (blockIdx.x < X_BLOCKS) {
        size_t base = ((size_t)blockIdx.x * 256 + threadIdx.x) * 16;
        cvt16(X, g_A, base);
    } else {
        size_t base = ((size_t)(blockIdx.x - X_BLOCKS) * 256 + threadIdx.x) * 16;
        cvt16(W, g_B, base);
    }
}

// ============================================================================
// GEMM + fused Taylor epilogue.  grid (N/256, M/128) = (32, 32), 512 threads.
// Warp grid 4(m) x 4(n); warp tile m32 x n64.
// ============================================================================
__global__ __launch_bounds__(512, 1)
void taylor_hmma_kernel(const float* __restrict__ D0, float* __restrict__ OUT)
{
    extern __shared__ __align__(128) char smem[];
    const uint32_t sb = smem_u32(smem);

    const int tid  = threadIdx.x;
    const int lane = tid & 31;
    const int wid  = tid >> 5;
    const int warp_m = wid >> 2;    // 0..3 -> m offset *32
    const int warp_n = wid & 3;     // 0..3 -> n offset *64

    const int bm = blockIdx.y * BM;
    const int bn = blockIdx.x * BN;

    // ---- cp.async mapping: 3 x 16B per thread per stage ----
    const int grow = tid >> 2;          // 0..127
    const int gc   = tid & 3;           // 16B chunk in 64B k-slab
    const __half* gA  = g_A + (size_t)(bm + grow) * K_IN + gc * 8;
    const __half* gB0 = g_B + (size_t)(bn + grow) * K_IN + gc * 8;
    const __half* gB1 = gB0 + (size_t)128 * K_IN;
    const uint32_t sAd  = sb + grow * ROWB + gc * 16;
    const uint32_t sBd0 = sb + A_BYTES + grow * ROWB + gc * 16;
    const uint32_t sBd1 = sBd0 + 128 * ROWB;

    float acc[2][8][4];
    #pragma unroll
    for (int mt = 0; mt < 2; mt++)
        #pragma unroll
        for (int nt = 0; nt < 8; nt++)
            #pragma unroll
            for (int r = 0; r < 4; r++) acc[mt][nt][r] = 0.0f;

    // ldmatrix lane addressing (proven layout)
    const int a_row  = warp_m * 32 + (lane & 15);
    const int a_chnk = lane >> 4;
    const int b_row  = warp_n * 64 + (lane & 7) + ((lane >> 4) & 1) * 8;
    const int b_chnk = (lane >> 3) & 1;

    // ---- pipeline prologue: fill STAGES-1 slots ----
    #pragma unroll
    for (int s = 0; s < STAGES - 1; s++) {
        const int k0 = s * BK;
        CP_ASYNC16(sAd  + s * STAGE_BYTES, gA  + k0);
        CP_ASYNC16(sBd0 + s * STAGE_BYTES, gB0 + k0);
        CP_ASYNC16(sBd1 + s * STAGE_BYTES, gB1 + k0);
        CP_COMMIT();
    }

    int cs = 0;                 // compute stage
    int ls = STAGES - 1;        // load stage
    for (int i = 0; i < NCH; i++) {
        CP_WAIT(STAGES - 2);
        __syncthreads();

        // refill the slot freed at iteration i-1
        if (i + STAGES - 1 < NCH) {
            const int k0 = (i + STAGES - 1) * BK;
            CP_ASYNC16(sAd  + ls * STAGE_BYTES, gA  + k0);
            CP_ASYNC16(sBd0 + ls * STAGE_BYTES, gB0 + k0);
            CP_ASYNC16(sBd1 + ls * STAGE_BYTES, gB1 + k0);
        }
        CP_COMMIT();   // one group per iteration keeps the ledger fixed

        const uint32_t aBase = sb + cs * STAGE_BYTES;
        const uint32_t bBase = aBase + A_BYTES;

        #pragma unroll
        for (int ks = 0; ks < 2; ks++) {            // two k16 steps per BK=32
            uint32_t a[2][4];
            #pragma unroll
            for (int mt = 0; mt < 2; mt++) {
                uint32_t addr = aBase + (a_row + mt * 16) * ROWB
                              + (ks * 2 + a_chnk) * 16;
                LDMATRIX_X4(a[mt][0], a[mt][1], a[mt][2], a[mt][3], addr);
            }
            uint32_t b[4][4];
            #pragma unroll
            for (int np = 0; np < 4; np++) {
                uint32_t addr = bBase + (b_row + np * 16) * ROWB
                              + (ks * 2 + b_chnk) * 16;
                LDMATRIX_X4(b[np][0], b[np][1], b[np][2], b[np][3], addr);
            }
            #pragma unroll
            for (int mt = 0; mt < 2; mt++)
                #pragma unroll
                for (int nt = 0; nt < 8; nt++)
                    MMA_F16(acc[mt][nt], a[mt],
                            b[nt >> 1][(nt & 1) * 2], b[nt >> 1][(nt & 1) * 2 + 1]);
        }
        __syncthreads();

        cs = (cs == STAGES - 1) ? 0 : cs + 1;
        ls = (ls == STAGES - 1) ? 0 : ls + 1;
    }

    // ---- fused Taylor epilogue ----
    // C frag m16n8: c0,c1 -> row lane>>2, cols 2*(lane&3)+{0,1}; c2,c3 -> row+8.
    // Each n8 tile is one o-group; gather its 8 cols across the lane quad.
    const int q = lane & ~3;
    #pragma unroll
    for (int nt = 0; nt < 8; nt++) {
        const int o = blockIdx.x * 32 + warp_n * 8 + nt;
        const float d0v = D0[o];
        #pragma unroll
        for (int mt = 0; mt < 2; mt++) {
            float c0 = acc[mt][nt][0], c1 = acc[mt][nt][1];
            float c2 = acc[mt][nt][2], c3 = acc[mt][nt][3];
            float t0[8], t1[8];
            #pragma unroll
            for (int d2 = 0; d2 < 4; d2++) {
                t0[2 * d2]     = __shfl_sync(0xffffffffu, c0, q + d2);
                t0[2 * d2 + 1] = __shfl_sync(0xffffffffu, c1, q + d2);
                t1[2 * d2]     = __shfl_sync(0xffffffffu, c2, q + d2);
                t1[2 * d2 + 1] = __shfl_sync(0xffffffffu, c3, q + d2);
            }
            float p0 = t0[0], s0 = t0[0];
            float p1 = t1[0], s1 = t1[0];
            #pragma unroll
            for (int d = 1; d < 8; d++) {
                p0 *= t0[d]; s0 += p0;
                p1 *= t1[d]; s1 += p1;
            }
            if ((lane & 3) == 0) {
                const int m0 = bm + warp_m * 32 + mt * 16 + (lane >> 2);
                OUT[(size_t)m0 * ODIM + o]       = d0v + s0;
                OUT[(size_t)(m0 + 8) * ODIM + o] = d0v + s1;
            }
        }
    }
}

// ============================================================================
// host side
// ============================================================================
extern "C" void kernel_launch(void* const* d_in, const int* in_sizes, int n_in,
                              void* d_out, int out_size)
{
    const float* x  = (const float*)d_in[0];   // [4096, 1024]
    const float* wt = (const float*)d_in[1];   // [1024, 8, 1024] = [8192, 1024]
    const float* d0 = (const float*)d_in[2];   // [1, 1024]
    float* out = (float*)d_out;                // [4096, 1024]

    convert_kernel<<<X_BLOCKS + W_BLOCKS, 256>>>(x, wt);

    cudaFuncSetAttribute(taylor_hmma_kernel,
                         cudaFuncAttributeMaxDynamicSharedMemorySize, SMEM_TOTAL);
    dim3 grid(N_TOTAL / BN, M_TOTAL / BM);     // (32, 32)
    taylor_hmma_kernel<<<grid, 512, SMEM_TOTAL>>>(d0, out);
}

// round 13
// speedup vs baseline: 3.6975x; 1.0515x over previous
#include <cuda_runtime.h>
#include <cuda_fp16.h>
#include <cstdint>

// ============================================================================
// TaylorLinearNet2 via HMMA (mma.sync fp16), portable sm_100 target.
//   t = X @ W^T  (M=4096, N=8192, K=1024), then per-8-col Taylor epilogue.
// Pure fp16 operands (calibrated rel_err 2.63e-4 << 1e-3).
// Round 11/12/13: register-fragment double buffering — LDSM for k-step ks+1
//   (and for the NEXT stage's ks=0) issues underneath the current 16-MMA burst,
//   removing the serialized LDSM-burst -> MMA-burst pattern ncu showed
//   (tensor=50%, L1=54%, both half-idle). CP_WAIT tightened to 2 so stage cs+1
//   is landed and barrier-visible before its fragments are prefetched.
// ============================================================================

#define M_TOTAL 4096
#define N_TOTAL 8192
#define K_IN    1024
#define ODIM    1024

#define BM 128
#define BN 256
#define BK 32
#define STAGES 5
#define NCH (K_IN / BK)         // 32

// smem rows: 32 fp16 data (64B) + 16B pad = 80 B; row r starts bank (20r mod 32)
#define ROWB 80
#define A_BYTES (BM * ROWB)             // 10240
#define B_BYTES (BN * ROWB)             // 20480
#define STAGE_BYTES (A_BYTES + B_BYTES) // 30720
#define SMEM_TOTAL (STAGES * STAGE_BYTES) // 153600

__device__ __align__(128) __half g_A[(size_t)M_TOTAL * K_IN]; // 8 MB
__device__ __align__(128) __half g_B[(size_t)N_TOTAL * K_IN]; // 16 MB

__device__ __forceinline__ uint32_t smem_u32(const void* p) {
    uint32_t a;
    asm("{ .reg .u64 t; cvta.to.shared.u64 t, %1; cvt.u32.u64 %0, t; }"
        : "=r"(a) : "l"(p));
    return a;
}

#define CP_ASYNC16(dst, src) \
    asm volatile("cp.async.cg.shared.global [%0], [%1], 16;" :: "r"(dst), "l"(src))
#define CP_COMMIT() asm volatile("cp.async.commit_group;" ::: "memory")
#define CP_WAIT(n)  asm volatile("cp.async.wait_group %0;" :: "n"(n) : "memory")

#define LDMATRIX_X4(r0, r1, r2, r3, addr) \
    asm volatile("ldmatrix.sync.aligned.m8n8.x4.shared.b16 {%0,%1,%2,%3}, [%4];" \
                 : "=r"(r0), "=r"(r1), "=r"(r2), "=r"(r3) : "r"(addr))

#define MMA_F16(acc, a, b0v, b1v) \
    asm volatile("mma.sync.aligned.m16n8k16.row.col.f32.f16.f16.f32 " \
                 "{%0,%1,%2,%3}, {%4,%5,%6,%7}, {%8,%9}, {%0,%1,%2,%3};" \
                 : "+f"((acc)[0]), "+f"((acc)[1]), "+f"((acc)[2]), "+f"((acc)[3]) \
                 : "r"((a)[0]), "r"((a)[1]), "r"((a)[2]), "r"((a)[3]), \
                   "r"(b0v), "r"(b1v))

// ============================================================================
// merged conversion kernel (round-10, measured good): 16 elems/thread, MLP=4
// ============================================================================
__device__ __forceinline__ uint32_t hpack2(float a, float b) {
    __half2 h; h.x = __float2half_rn(a); h.y = __float2half_rn(b);
    return *reinterpret_cast<uint32_t*>(&h);
}

__device__ __forceinline__ void cvt16(const float* __restrict__ src,
                                      __half* __restrict__ dst, size_t base) {
    const float4* s4 = reinterpret_cast<const float4*>(src + base);
    float4 v0 = s4[0], v1 = s4[1], v2 = s4[2], v3 = s4[3];   // 4-wide MLP
    uint4 h0, h1;
    h0.x = hpack2(v0.x, v0.y);  h0.y = hpack2(v0.z, v0.w);
    h0.z = hpack2(v1.x, v1.y);  h0.w = hpack2(v1.z, v1.w);
    h1.x = hpack2(v2.x, v2.y);  h1.y = hpack2(v2.z, v2.w);
    h1.z = hpack2(v3.x, v3.y);  h1.w = hpack2(v3.z, v3.w);
    *reinterpret_cast<uint4*>(dst + base)     = h0;
    *reinterpret_cast<uint4*>(dst + base + 8) = h1;
}

#define X_BLOCKS 1024   // 1024 * 256 * 16 = M*K
#define W_BLOCKS 2048   // 2048 * 256 * 16 = N*K

__global__ void convert_kernel(const float* __restrict__ X,
                               const float* __restrict__ W) {
    if (blockIdx.x < X_BLOCKS) {
        size_t base = ((size_t)blockIdx.x * 256 + threadIdx.x) * 16;
        cvt16(X, g_A, base);
    } else {
        size_t base = ((size_t)(blockIdx.x - X_BLOCKS) * 256 + threadIdx.x) * 16;
        cvt16(W, g_B, base);
    }
}

// ============================================================================
// GEMM + fused Taylor epilogue.  grid (N/256, M/128) = (32, 32), 512 threads.
// Warp grid 4(m) x 4(n); warp tile m32 x n64.
// ============================================================================
__global__ __launch_bounds__(512, 1)
void taylor_hmma_kernel(const float* __restrict__ D0, float* __restrict__ OUT)
{
    extern __shared__ __align__(128) char smem[];
    const uint32_t sb = smem_u32(smem);

    const int tid  = threadIdx.x;
    const int lane = tid & 31;
    const int wid  = tid >> 5;
    const int warp_m = wid >> 2;    // 0..3 -> m offset *32
    const int warp_n = wid & 3;     // 0..3 -> n offset *64

    const int bm = blockIdx.y * BM;
    const int bn = blockIdx.x * BN;

    // ---- cp.async mapping: 3 x 16B per thread per stage ----
    const int grow = tid >> 2;          // 0..127
    const int gc   = tid & 3;           // 16B chunk in 64B k-slab
    const __half* gA  = g_A + (size_t)(bm + grow) * K_IN + gc * 8;
    const __half* gB0 = g_B + (size_t)(bn + grow) * K_IN + gc * 8;
    const __half* gB1 = gB0 + (size_t)128 * K_IN;
    const uint32_t sAd  = sb + grow * ROWB + gc * 16;
    const uint32_t sBd0 = sb + A_BYTES + grow * ROWB + gc * 16;
    const uint32_t sBd1 = sBd0 + 128 * ROWB;

    float acc[2][8][4];
    #pragma unroll
    for (int mt = 0; mt < 2; mt++)
        #pragma unroll
        for (int nt = 0; nt < 8; nt++)
            #pragma unroll
            for (int r = 0; r < 4; r++) acc[mt][nt][r] = 0.0f;

    // per-warp ldmatrix offsets within a stage (add stage base + ks*32)
    const uint32_t aOff = (uint32_t)((warp_m * 32 + (lane & 15)) * ROWB
                                     + (lane >> 4) * 16);
    const uint32_t bOff = (uint32_t)(A_BYTES
                        + (warp_n * 64 + (lane & 7) + ((lane >> 4) & 1) * 8) * ROWB
                        + ((lane >> 3) & 1) * 16);

    // double-buffered fragments
    uint32_t af[2][2][4];   // [buf][mt][reg]
    uint32_t bf[2][4][4];   // [buf][np][reg]

    // ---- pipeline prologue: fill stages 0..3 ----
    #pragma unroll
    for (int s = 0; s < STAGES - 1; s++) {
        const int k0 = s * BK;
        CP_ASYNC16(sAd  + s * STAGE_BYTES, gA  + k0);
        CP_ASYNC16(sBd0 + s * STAGE_BYTES, gB0 + k0);
        CP_ASYNC16(sBd1 + s * STAGE_BYTES, gB1 + k0);
        CP_COMMIT();
    }
    CP_WAIT(2);             // stages 0,1 landed
    __syncthreads();        // ... and visible to all threads

    // prefetch (stage 0, ks 0) fragments into buffer 0
    #pragma unroll
    for (int mt = 0; mt < 2; mt++)
        LDMATRIX_X4(af[0][mt][0], af[0][mt][1], af[0][mt][2], af[0][mt][3],
                    sb + aOff + mt * 16 * ROWB);
    #pragma unroll
    for (int np = 0; np < 4; np++)
        LDMATRIX_X4(bf[0][np][0], bf[0][np][1], bf[0][np][2], bf[0][np][3],
                    sb + bOff + np * 16 * ROWB);

    int cs = 0;                 // compute stage
    int ls = STAGES - 1;        // load stage
    for (int i = 0; i < NCH; i++) {
        CP_WAIT(2);             // forces stage i+1 landed (group g = stage g-1)
        __syncthreads();        // visibility + WAR protection for refill below

        if (i + STAGES - 1 < NCH) {
            const int k0 = (i + STAGES - 1) * BK;
            CP_ASYNC16(sAd  + ls * STAGE_BYTES, gA  + k0);
            CP_ASYNC16(sBd0 + ls * STAGE_BYTES, gB0 + k0);
            CP_ASYNC16(sBd1 + ls * STAGE_BYTES, gB1 + k0);
        }
        CP_COMMIT();            // one group per iteration keeps the ledger fixed

        const uint32_t curBase = sb + cs * STAGE_BYTES;
        const int cs1 = (cs == STAGES - 1) ? 0 : cs + 1;
        const uint32_t nxtBase = sb + cs1 * STAGE_BYTES;

        // ---- ks = 0: prefetch (cs, ks=1) into buf 1; MMA with buf 0 ----
        #pragma unroll
        for (int mt = 0; mt < 2; mt++)
            LDMATRIX_X4(af[1][mt][0], af[1][mt][1], af[1][mt][2], af[1][mt][3],
                        curBase + aOff + mt * 16 * ROWB + 32);
        #pragma unroll
        for (int np = 0; np < 4; np++)
            LDMATRIX_X4(bf[1][np][0], bf[1][np][1], bf[1][np][2], bf[1][np][3],
                        curBase + bOff + np * 16 * ROWB + 32);
        #pragma unroll
        for (int mt = 0; mt < 2; mt++)
            #pragma unroll
            for (int nt = 0; nt < 8; nt++)
                MMA_F16(acc[mt][nt], af[0][mt],
                        bf[0][nt >> 1][(nt & 1) * 2], bf[0][nt >> 1][(nt & 1) * 2 + 1]);

        // ---- ks = 1: prefetch (cs+1, ks=0) into buf 0; MMA with buf 1 ----
        // (stage cs+1 is landed+visible; reads are harmless-garbage on the
        //  final iteration and simply unused)
        #pragma unroll
        for (int mt = 0; mt < 2; mt++)
            LDMATRIX_X4(af[0][mt][0], af[0][mt][1], af[0][mt][2], af[0][mt][3],
                        nxtBase + aOff + mt * 16 * ROWB);
        #pragma unroll
        for (int np = 0; np < 4; np++)
            LDMATRIX_X4(bf[0][np][0], bf[0][np][1], bf[0][np][2], bf[0][np][3],
                        nxtBase + bOff + np * 16 * ROWB);
        #pragma unroll
        for (int mt = 0; mt < 2; mt++)
            #pragma unroll
            for (int nt = 0; nt < 8; nt++)
                MMA_F16(acc[mt][nt], af[1][mt],
                        bf[1][nt >> 1][(nt & 1) * 2], bf[1][nt >> 1][(nt & 1) * 2 + 1]);

        cs = cs1;
        ls = (ls == STAGES - 1) ? 0 : ls + 1;
    }

    // ---- fused Taylor epilogue ----
    // C frag m16n8: c0,c1 -> row lane>>2, cols 2*(lane&3)+{0,1}; c2,c3 -> row+8.
    // Each n8 tile is one o-group; gather its 8 cols across the lane quad.
    const int q = lane & ~3;
    #pragma unroll
    for (int nt = 0; nt < 8; nt++) {
        const int o = blockIdx.x * 32 + warp_n * 8 + nt;
        const float d0v = D0[o];
        #pragma unroll
        for (int mt = 0; mt < 2; mt++) {
            float c0 = acc[mt][nt][0], c1 = acc[mt][nt][1];
            float c2 = acc[mt][nt][2], c3 = acc[mt][nt][3];
            float t0[8], t1[8];
            #pragma unroll
            for (int d2 = 0; d2 < 4; d2++) {
                t0[2 * d2]     = __shfl_sync(0xffffffffu, c0, q + d2);
                t0[2 * d2 + 1] = __shfl_sync(0xffffffffu, c1, q + d2);
                t1[2 * d2]     = __shfl_sync(0xffffffffu, c2, q + d2);
                t1[2 * d2 + 1] = __shfl_sync(0xffffffffu, c3, q + d2);
            }
            float p0 = t0[0], s0 = t0[0];
            float p1 = t1[0], s1 = t1[0];
            #pragma unroll
            for (int d = 1; d < 8; d++) {
                p0 *= t0[d]; s0 += p0;
                p1 *= t1[d]; s1 += p1;
            }
            if ((lane & 3) == 0) {
                const int m0 = bm + warp_m * 32 + mt * 16 + (lane >> 2);
                OUT[(size_t)m0 * ODIM + o]       = d0v + s0;
                OUT[(size_t)(m0 + 8) * ODIM + o] = d0v + s1;
            }
        }
    }
}

// ============================================================================
// host side
// ============================================================================
extern "C" void kernel_launch(void* const* d_in, const int* in_sizes, int n_in,
                              void* d_out, int out_size)
{
    const float* x  = (const float*)d_in[0];   // [4096, 1024]
    const float* wt = (const float*)d_in[1];   // [1024, 8, 1024] = [8192, 1024]
    const float* d0 = (const float*)d_in[2];   // [1, 1024]
    float* out = (float*)d_out;                // [4096, 1024]

    convert_kernel<<<X_BLOCKS + W_BLOCKS, 256>>>(x, wt);

    cudaFuncSetAttribute(taylor_hmma_kernel,
                         cudaFuncAttributeMaxDynamicSharedMemorySize, SMEM_TOTAL);
    dim3 grid(N_TOTAL / BN, M_TOTAL / BM);     // (32, 32)
    taylor_hmma_kernel<<<grid, 512, SMEM_TOTAL>>>(d0, out);
}

// round 14
// speedup vs baseline: 3.7229x; 1.0069x over previous
#include <cuda_runtime.h>
#include <cuda_fp16.h>
#include <cstdint>

// ============================================================================
// TaylorLinearNet2 via HMMA (mma.sync fp16), portable sm_100 target.
//   t = X @ W^T  (M=4096, N=8192, K=1024), then per-8-col Taylor epilogue.
// Pure fp16 operands (calibrated rel_err 2.63e-4 << 1e-3).
// Round 14: spill relief. regs were pinned at the 128 cap (64 acc + 48 frag +
//   addresses) -> suspected local-memory spills canceling the round-13 overlap
//   win. A-fragments now SINGLE-buffered (reloaded per k-step, ~60 cyc/iter
//   exposure), B-fragments stay double-buffered. Target ~119 regs, no spills.
// ============================================================================

#define M_TOTAL 4096
#define N_TOTAL 8192
#define K_IN    1024
#define ODIM    1024

#define BM 128
#define BN 256
#define BK 32
#define STAGES 5
#define NCH (K_IN / BK)         // 32

// smem rows: 32 fp16 data (64B) + 16B pad = 80 B; row r starts bank (20r mod 32)
#define ROWB 80
#define A_BYTES (BM * ROWB)             // 10240
#define B_BYTES (BN * ROWB)             // 20480
#define STAGE_BYTES (A_BYTES + B_BYTES) // 30720
#define SMEM_TOTAL (STAGES * STAGE_BYTES) // 153600

__device__ __align__(128) __half g_A[(size_t)M_TOTAL * K_IN]; // 8 MB
__device__ __align__(128) __half g_B[(size_t)N_TOTAL * K_IN]; // 16 MB

__device__ __forceinline__ uint32_t smem_u32(const void* p) {
    uint32_t a;
    asm("{ .reg .u64 t; cvta.to.shared.u64 t, %1; cvt.u32.u64 %0, t; }"
        : "=r"(a) : "l"(p));
    return a;
}

#define CP_ASYNC16(dst, src) \
    asm volatile("cp.async.cg.shared.global [%0], [%1], 16;" :: "r"(dst), "l"(src))
#define CP_COMMIT() asm volatile("cp.async.commit_group;" ::: "memory")
#define CP_WAIT(n)  asm volatile("cp.async.wait_group %0;" :: "n"(n) : "memory")

#define LDMATRIX_X4(r0, r1, r2, r3, addr) \
    asm volatile("ldmatrix.sync.aligned.m8n8.x4.shared.b16 {%0,%1,%2,%3}, [%4];" \
                 : "=r"(r0), "=r"(r1), "=r"(r2), "=r"(r3) : "r"(addr))

#define MMA_F16(acc, a, b0v, b1v) \
    asm volatile("mma.sync.aligned.m16n8k16.row.col.f32.f16.f16.f32 " \
                 "{%0,%1,%2,%3}, {%4,%5,%6,%7}, {%8,%9}, {%0,%1,%2,%3};" \
                 : "+f"((acc)[0]), "+f"((acc)[1]), "+f"((acc)[2]), "+f"((acc)[3]) \
                 : "r"((a)[0]), "r"((a)[1]), "r"((a)[2]), "r"((a)[3]), \
                   "r"(b0v), "r"(b1v))

// ============================================================================
// merged conversion kernel (round-10, measured good): 16 elems/thread, MLP=4
// ============================================================================
__device__ __forceinline__ uint32_t hpack2(float a, float b) {
    __half2 h; h.x = __float2half_rn(a); h.y = __float2half_rn(b);
    return *reinterpret_cast<uint32_t*>(&h);
}

__device__ __forceinline__ void cvt16(const float* __restrict__ src,
                                      __half* __restrict__ dst, size_t base) {
    const float4* s4 = reinterpret_cast<const float4*>(src + base);
    float4 v0 = s4[0], v1 = s4[1], v2 = s4[2], v3 = s4[3];   // 4-wide MLP
    uint4 h0, h1;
    h0.x = hpack2(v0.x, v0.y);  h0.y = hpack2(v0.z, v0.w);
    h0.z = hpack2(v1.x, v1.y);  h0.w = hpack2(v1.z, v1.w);
    h1.x = hpack2(v2.x, v2.y);  h1.y = hpack2(v2.z, v2.w);
    h1.z = hpack2(v3.x, v3.y);  h1.w = hpack2(v3.z, v3.w);
    *reinterpret_cast<uint4*>(dst + base)     = h0;
    *reinterpret_cast<uint4*>(dst + base + 8) = h1;
}

#define X_BLOCKS 1024   // 1024 * 256 * 16 = M*K
#define W_BLOCKS 2048   // 2048 * 256 * 16 = N*K

__global__ void convert_kernel(const float* __restrict__ X,
                               const float* __restrict__ W) {
    if (blockIdx.x < X_BLOCKS) {
        size_t base = ((size_t)blockIdx.x * 256 + threadIdx.x) * 16;
        cvt16(X, g_A, base);
    } else {
        size_t base = ((size_t)(blockIdx.x - X_BLOCKS) * 256 + threadIdx.x) * 16;
        cvt16(W, g_B, base);
    }
}

// ============================================================================
// GEMM + fused Taylor epilogue.  grid (N/256, M/128) = (32, 32), 512 threads.
// Warp grid 4(m) x 4(n); warp tile m32 x n64.
// ============================================================================
__global__ __launch_bounds__(512, 1)
void taylor_hmma_kernel(const float* __restrict__ D0, float* __restrict__ OUT)
{
    extern __shared__ __align__(128) char smem[];
    const uint32_t sb = smem_u32(smem);

    const int tid  = threadIdx.x;
    const int lane = tid & 31;
    const int wid  = tid >> 5;
    const int warp_m = wid >> 2;    // 0..3 -> m offset *32
    const int warp_n = wid & 3;     // 0..3 -> n offset *64

    const int bm = blockIdx.y * BM;
    const int bn = blockIdx.x * BN;

    // ---- cp.async mapping: 3 x 16B per thread per stage ----
    const int grow = tid >> 2;          // 0..127
    const int gc   = tid & 3;           // 16B chunk in 64B k-slab
    const __half* gA  = g_A + (size_t)(bm + grow) * K_IN + gc * 8;
    const __half* gB0 = g_B + (size_t)(bn + grow) * K_IN + gc * 8;
    const __half* gB1 = gB0 + (size_t)128 * K_IN;
    const uint32_t sAd  = sb + grow * ROWB + gc * 16;
    const uint32_t sBd0 = sb + A_BYTES + grow * ROWB + gc * 16;
    const uint32_t sBd1 = sBd0 + 128 * ROWB;

    float acc[2][8][4];
    #pragma unroll
    for (int mt = 0; mt < 2; mt++)
        #pragma unroll
        for (int nt = 0; nt < 8; nt++)
            #pragma unroll
            for (int r = 0; r < 4; r++) acc[mt][nt][r] = 0.0f;

    // per-warp ldmatrix offsets within a stage (add stage base + ks*32)
    const uint32_t aOff = (uint32_t)((warp_m * 32 + (lane & 15)) * ROWB
                                     + (lane >> 4) * 16);
    const uint32_t bOff = (uint32_t)(A_BYTES
                        + (warp_n * 64 + (lane & 7) + ((lane >> 4) & 1) * 8) * ROWB
                        + ((lane >> 3) & 1) * 16);

    // A fragments single-buffered (reloaded per k-step); B double-buffered
    uint32_t af[2][4];      // [mt][reg]
    uint32_t bf[2][4][4];   // [buf][np][reg]

    // ---- pipeline prologue: fill stages 0..3 ----
    #pragma unroll
    for (int s = 0; s < STAGES - 1; s++) {
        const int k0 = s * BK;
        CP_ASYNC16(sAd  + s * STAGE_BYTES, gA  + k0);
        CP_ASYNC16(sBd0 + s * STAGE_BYTES, gB0 + k0);
        CP_ASYNC16(sBd1 + s * STAGE_BYTES, gB1 + k0);
        CP_COMMIT();
    }
    CP_WAIT(2);             // stages 0,1 landed
    __syncthreads();        // ... and visible to all threads

    // prefetch (stage 0, ks 0): af and bf[0]
    #pragma unroll
    for (int mt = 0; mt < 2; mt++)
        LDMATRIX_X4(af[mt][0], af[mt][1], af[mt][2], af[mt][3],
                    sb + aOff + mt * 16 * ROWB);
    #pragma unroll
    for (int np = 0; np < 4; np++)
        LDMATRIX_X4(bf[0][np][0], bf[0][np][1], bf[0][np][2], bf[0][np][3],
                    sb + bOff + np * 16 * ROWB);

    int cs = 0;                 // compute stage
    int ls = STAGES - 1;        // load stage
    for (int i = 0; i < NCH; i++) {
        CP_WAIT(2);             // forces stage i+1 landed (group g = stage g-1)
        __syncthreads();        // visibility + WAR protection for refill below

        if (i + STAGES - 1 < NCH) {
            const int k0 = (i + STAGES - 1) * BK;
            CP_ASYNC16(sAd  + ls * STAGE_BYTES, gA  + k0);
            CP_ASYNC16(sBd0 + ls * STAGE_BYTES, gB0 + k0);
            CP_ASYNC16(sBd1 + ls * STAGE_BYTES, gB1 + k0);
        }
        CP_COMMIT();            // one group per iteration keeps the ledger fixed

        const uint32_t curBase = sb + cs * STAGE_BYTES;
        const int cs1 = (cs == STAGES - 1) ? 0 : cs + 1;
        const uint32_t nxtBase = sb + cs1 * STAGE_BYTES;

        // ---- ks = 0: prefetch bf[1] <- (cs, ks1); MMA with (af, bf[0]);
        //              then reload af <- (cs, ks1) ----
        #pragma unroll
        for (int np = 0; np < 4; np++)
            LDMATRIX_X4(bf[1][np][0], bf[1][np][1], bf[1][np][2], bf[1][np][3],
                        curBase + bOff + np * 16 * ROWB + 32);
        #pragma unroll
        for (int mt = 0; mt < 2; mt++)
            #pragma unroll
            for (int nt = 0; nt < 8; nt++)
                MMA_F16(acc[mt][nt], af[mt],
                        bf[0][nt >> 1][(nt & 1) * 2], bf[0][nt >> 1][(nt & 1) * 2 + 1]);
        #pragma unroll
        for (int mt = 0; mt < 2; mt++)
            LDMATRIX_X4(af[mt][0], af[mt][1], af[mt][2], af[mt][3],
                        curBase + aOff + mt * 16 * ROWB + 32);

        // ---- ks = 1: prefetch bf[0] <- (cs+1, ks0); MMA with (af, bf[1]);
        //              then reload af <- (cs+1, ks0) ----
        // (stage cs+1 is landed+visible; final-iteration reads are unused garbage)
        #pragma unroll
        for (int np = 0; np < 4; np++)
            LDMATRIX_X4(bf[0][np][0], bf[0][np][1], bf[0][np][2], bf[0][np][3],
                        nxtBase + bOff + np * 16 * ROWB);
        #pragma unroll
        for (int mt = 0; mt < 2; mt++)
            #pragma unroll
            for (int nt = 0; nt < 8; nt++)
                MMA_F16(acc[mt][nt], af[mt],
                        bf[1][nt >> 1][(nt & 1) * 2], bf[1][nt >> 1][(nt & 1) * 2 + 1]);
        #pragma unroll
        for (int mt = 0; mt < 2; mt++)
            LDMATRIX_X4(af[mt][0], af[mt][1], af[mt][2], af[mt][3],
                        nxtBase + aOff + mt * 16 * ROWB);

        cs = cs1;
        ls = (ls == STAGES - 1) ? 0 : ls + 1;
    }

    // ---- fused Taylor epilogue ----
    // C frag m16n8: c0,c1 -> row lane>>2, cols 2*(lane&3)+{0,1}; c2,c3 -> row+8.
    // Each n8 tile is one o-group; gather its 8 cols across the lane quad.
    const int q = lane & ~3;
    #pragma unroll
    for (int nt = 0; nt < 8; nt++) {
        const int o = blockIdx.x * 32 + warp_n * 8 + nt;
        const float d0v = D0[o];
        #pragma unroll
        for (int mt = 0; mt < 2; mt++) {
            float c0 = acc[mt][nt][0], c1 = acc[mt][nt][1];
            float c2 = acc[mt][nt][2], c3 = acc[mt][nt][3];
            float t0[8], t1[8];
            #pragma unroll
            for (int d2 = 0; d2 < 4; d2++) {
                t0[2 * d2]     = __shfl_sync(0xffffffffu, c0, q + d2);
                t0[2 * d2 + 1] = __shfl_sync(0xffffffffu, c1, q + d2);
                t1[2 * d2]     = __shfl_sync(0xffffffffu, c2, q + d2);
                t1[2 * d2 + 1] = __shfl_sync(0xffffffffu, c3, q + d2);
            }
            float p0 = t0[0], s0 = t0[0];
            float p1 = t1[0], s1 = t1[0];
            #pragma unroll
            for (int d = 1; d < 8; d++) {
                p0 *= t0[d]; s0 += p0;
                p1 *= t1[d]; s1 += p1;
            }
            if ((lane & 3) == 0) {
                const int m0 = bm + warp_m * 32 + mt * 16 + (lane >> 2);
                OUT[(size_t)m0 * ODIM + o]       = d0v + s0;
                OUT[(size_t)(m0 + 8) * ODIM + o] = d0v + s1;
            }
        }
    }
}

// ============================================================================
// host side
// ============================================================================
extern "C" void kernel_launch(void* const* d_in, const int* in_sizes, int n_in,
                              void* d_out, int out_size)
{
    const float* x  = (const float*)d_in[0];   // [4096, 1024]
    const float* wt = (const float*)d_in[1];   // [1024, 8, 1024] = [8192, 1024]
    const float* d0 = (const float*)d_in[2];   // [1, 1024]
    float* out = (float*)d_out;                // [4096, 1024]

    convert_kernel<<<X_BLOCKS + W_BLOCKS, 256>>>(x, wt);

    cudaFuncSetAttribute(taylor_hmma_kernel,
                         cudaFuncAttributeMaxDynamicSharedMemorySize, SMEM_TOTAL);
    dim3 grid(N_TOTAL / BN, M_TOTAL / BM);     // (32, 32)
    taylor_hmma_kernel<<<grid, 512, SMEM_TOTAL>>>(d0, out);
}